// round 7
// baseline (speedup 1.0000x reference)
#include <cuda_runtime.h>
#include <cuda_bf16.h>
#include <cstdint>

#define N_NODES 50000
#define N_EDGES 600000
#define D 128

// ---------------------------------------------------------------------------
// Scratch (allocation-free rule: __device__ globals)
// ---------------------------------------------------------------------------
__device__ float g_h[(size_t)N_NODES * D];     // layer-1 activations
__device__ int   g_deg[N_NODES];
__device__ int   g_cursor[N_NODES];
__device__ int   g_rowptr[N_NODES + 1];
__device__ int   g_esrc[N_EDGES];

__device__ __forceinline__ float to_tf32(float f) {
    float r;
    asm("cvt.rna.tf32.f32 %0, %1;" : "=f"(r) : "f"(f));
    return r;
}

// ---------------------------------------------------------------------------
// CSR build: 4 kernels total
// ---------------------------------------------------------------------------
__global__ void zero_deg() {
    int i = blockIdx.x * blockDim.x + threadIdx.x;
    if (i < N_NODES) g_deg[i] = 0;
}

__global__ void hist_kernel(const int* __restrict__ eidx) {
    int e = blockIdx.x * blockDim.x + threadIdx.x;
    if (e < N_EDGES) atomicAdd(&g_deg[__ldg(&eidx[N_EDGES + e])], 1);
}

// Single-CTA scan over all 50000 degrees: thread t owns 49 contiguous nodes.
// Emits rowptr (inclusive shifted) AND cursor (= exclusive prefix) for fill.
__global__ void scan_fused() {
    __shared__ int wsum[32];
    const int C = (N_NODES + 1023) / 1024;   // 49
    int t = threadIdx.x, lane = t & 31, w = t >> 5;
    int beg = t * C, end = min(beg + C, N_NODES);

    int local = 0;
    for (int i = beg; i < end; i++) local += g_deg[i];

    int inc = local;
#pragma unroll
    for (int o = 1; o < 32; o <<= 1) {
        int u = __shfl_up_sync(0xffffffffu, inc, o);
        if (lane >= o) inc += u;
    }
    if (lane == 31) wsum[w] = inc;
    __syncthreads();
    if (w == 0) {
        int v = wsum[lane];
        int i2 = v;
#pragma unroll
        for (int o = 1; o < 32; o <<= 1) {
            int u = __shfl_up_sync(0xffffffffu, i2, o);
            if (lane >= o) i2 += u;
        }
        wsum[lane] = i2 - v;   // exclusive warp offsets
    }
    __syncthreads();

    int run = wsum[w] + (inc - local);   // thread's exclusive prefix
    for (int i = beg; i < end; i++) {
        int d = g_deg[i];
        g_cursor[i] = run;
        run += d;
        g_rowptr[i + 1] = run;
    }
    if (t == 0) g_rowptr[0] = 0;
}

__global__ void fill_kernel(const int* __restrict__ eidx) {
    int e = blockIdx.x * blockDim.x + threadIdx.x;
    if (e >= N_EDGES) return;
    int s = __ldg(&eidx[e]);
    int d = __ldg(&eidx[N_EDGES + e]);
    int slot = atomicAdd(&g_cursor[d], 1);
    g_esrc[slot] = s;
}

// ---------------------------------------------------------------------------
// Fused gather + tf32 mma GEMM: out = mean @ Wl + feat @ Wr + b (+relu L1)
// CTA = 128 rows x 128 cols, 8 warps. Phase G: each warp computes the mean
// of its 16 rows straight into the SMEM A tile (tf32-rounded). Then two
// K=128 mma passes (mean@Wl, feat@Wr) with fp32 register accumulators.
// ---------------------------------------------------------------------------
#define ASA 132
#define WSB 136
#define TCSM ((128 * ASA + 128 * WSB) * 4)   // 134 KB

__device__ __forceinline__ void mma_tf32(float c[4], uint32_t a0, uint32_t a1,
                                         uint32_t a2, uint32_t a3,
                                         uint32_t b0, uint32_t b1) {
    asm volatile(
        "mma.sync.aligned.m16n8k8.row.col.f32.tf32.tf32.f32 "
        "{%0,%1,%2,%3}, {%4,%5,%6,%7}, {%8,%9}, {%0,%1,%2,%3};"
        : "+f"(c[0]), "+f"(c[1]), "+f"(c[2]), "+f"(c[3])
        : "r"(a0), "r"(a1), "r"(a2), "r"(a3), "r"(b0), "r"(b1));
}

template <int LAYER>
__global__ void __launch_bounds__(256, 1)
sage_gemm_fused(const float* __restrict__ x_in,
                const float* __restrict__ Wl, const float* __restrict__ Wr,
                const float* __restrict__ bias, float* __restrict__ d_out) {
    extern __shared__ float sm[];
    float* sA = sm;                 // [128][ASA]
    float* sW = sm + 128 * ASA;     // [128][WSB]

    int tid = threadIdx.x;
    int wid = tid >> 5;
    int lane = tid & 31;
    int gid = lane >> 2;            // 0..7
    int tig = lane & 3;             // 0..3
    int base = blockIdx.x * 128;

    const float* feat = (LAYER == 1) ? x_in : g_h;
    float* out        = (LAYER == 1) ? g_h : d_out;

    // ---- Phase G: gather means for this CTA's 128 rows into sA ----
    for (int rr = 0; rr < 16; rr++) {
        int r = wid * 16 + rr;
        int g = base + r;
        float4 acc = make_float4(0.f, 0.f, 0.f, 0.f);
        if (g < N_NODES) {
            int beg = __ldg(&g_rowptr[g]);
            int end = __ldg(&g_rowptr[g + 1]);
            int j = beg;
            for (; j + 4 <= end; j += 4) {
                int s0 = __ldg(&g_esrc[j + 0]);
                int s1 = __ldg(&g_esrc[j + 1]);
                int s2 = __ldg(&g_esrc[j + 2]);
                int s3 = __ldg(&g_esrc[j + 3]);
                float4 v0 = __ldg(reinterpret_cast<const float4*>(feat + (size_t)s0 * D) + lane);
                float4 v1 = __ldg(reinterpret_cast<const float4*>(feat + (size_t)s1 * D) + lane);
                float4 v2 = __ldg(reinterpret_cast<const float4*>(feat + (size_t)s2 * D) + lane);
                float4 v3 = __ldg(reinterpret_cast<const float4*>(feat + (size_t)s3 * D) + lane);
                acc.x += (v0.x + v1.x) + (v2.x + v3.x);
                acc.y += (v0.y + v1.y) + (v2.y + v3.y);
                acc.z += (v0.z + v1.z) + (v2.z + v3.z);
                acc.w += (v0.w + v1.w) + (v2.w + v3.w);
            }
            for (; j < end; j++) {
                int s = __ldg(&g_esrc[j]);
                float4 v = __ldg(reinterpret_cast<const float4*>(feat + (size_t)s * D) + lane);
                acc.x += v.x; acc.y += v.y; acc.z += v.z; acc.w += v.w;
            }
            float inv = 1.0f / fmaxf((float)(end - beg), 1.0f);
            acc.x *= inv; acc.y *= inv; acc.z *= inv; acc.w *= inv;
        }
        acc.x = to_tf32(acc.x); acc.y = to_tf32(acc.y);
        acc.z = to_tf32(acc.z); acc.w = to_tf32(acc.w);
        *reinterpret_cast<float4*>(sA + r * ASA + lane * 4) = acc;
    }

    float c[16][4];
#pragma unroll
    for (int nt = 0; nt < 16; nt++)
#pragma unroll
        for (int q = 0; q < 4; q++) c[nt][q] = 0.f;

#pragma unroll
    for (int pass = 0; pass < 2; pass++) {
        const float* Wsrc = (pass == 0) ? Wl : Wr;

        if (pass) {
            __syncthreads();   // pass-0 tiles fully consumed
            // Stage A = feat rows
            for (int e = tid; e < 128 * 32; e += 256) {
                int r = e >> 5, c4 = e & 31;
                int g = base + r;
                float4 v = make_float4(0.f, 0.f, 0.f, 0.f);
                if (g < N_NODES)
                    v = __ldg(reinterpret_cast<const float4*>(feat + (size_t)g * D) + c4);
                v.x = to_tf32(v.x); v.y = to_tf32(v.y);
                v.z = to_tf32(v.z); v.w = to_tf32(v.w);
                *reinterpret_cast<float4*>(sA + r * ASA + c4 * 4) = v;
            }
        }
        // Stage W (row-major [k][n], consumed as col-frag B)
        for (int e = tid; e < 128 * 32; e += 256) {
            int r = e >> 5, c4 = e & 31;
            float4 v = __ldg(reinterpret_cast<const float4*>(Wsrc + (size_t)r * D) + c4);
            v.x = to_tf32(v.x); v.y = to_tf32(v.y);
            v.z = to_tf32(v.z); v.w = to_tf32(v.w);
            *reinterpret_cast<float4*>(sW + r * WSB + c4 * 4) = v;
        }
        __syncthreads();

        const float* Awarp = sA + (wid * 16 + gid) * ASA + tig;
#pragma unroll 4
        for (int ks = 0; ks < 16; ks++) {
            const float* ap = Awarp + ks * 8;
            uint32_t a0 = __float_as_uint(ap[0]);
            uint32_t a1 = __float_as_uint(ap[8 * ASA]);
            uint32_t a2 = __float_as_uint(ap[4]);
            uint32_t a3 = __float_as_uint(ap[8 * ASA + 4]);
            const float* bp = sW + (ks * 8 + tig) * WSB + gid;
#pragma unroll
            for (int nt = 0; nt < 16; nt++) {
                uint32_t b0 = __float_as_uint(bp[nt * 8]);
                uint32_t b1 = __float_as_uint(bp[4 * WSB + nt * 8]);
                mma_tf32(c[nt], a0, a1, a2, a3, b0, b1);
            }
        }
    }

    // Epilogue: bias (+relu), direct register->gmem store
    int row0 = base + wid * 16 + gid;
#pragma unroll
    for (int nt = 0; nt < 16; nt++) {
        int col = nt * 8 + 2 * tig;
        float2 bb = *reinterpret_cast<const float2*>(bias + col);
        float o0 = c[nt][0] + bb.x, o1 = c[nt][1] + bb.y;
        float o2 = c[nt][2] + bb.x, o3 = c[nt][3] + bb.y;
        if (LAYER == 1) {
            o0 = fmaxf(o0, 0.f); o1 = fmaxf(o1, 0.f);
            o2 = fmaxf(o2, 0.f); o3 = fmaxf(o3, 0.f);
        }
        if (row0 < N_NODES)
            *reinterpret_cast<float2*>(out + (size_t)row0 * D + col) = make_float2(o0, o1);
        if (row0 + 8 < N_NODES)
            *reinterpret_cast<float2*>(out + (size_t)(row0 + 8) * D + col) = make_float2(o2, o3);
    }
}

// ---------------------------------------------------------------------------
extern "C" void kernel_launch(void* const* d_in, const int* in_sizes, int n_in,
                              void* d_out, int out_size) {
    const float* x       = (const float*)d_in[0];
    const int* ei        = (const int*)d_in[1];   // int32 (JAX x64 disabled)
    const float* Wl1     = (const float*)d_in[2];
    const float* Wr1     = (const float*)d_in[3];
    const float* b1      = (const float*)d_in[4];
    const float* Wl2     = (const float*)d_in[5];
    const float* Wr2     = (const float*)d_in[6];
    const float* b2      = (const float*)d_in[7];
    float* out           = (float*)d_out;

    cudaFuncSetAttribute(sage_gemm_fused<1>,
                         cudaFuncAttributeMaxDynamicSharedMemorySize, TCSM);
    cudaFuncSetAttribute(sage_gemm_fused<2>,
                         cudaFuncAttributeMaxDynamicSharedMemorySize, TCSM);

    int eb = (N_EDGES + 255) / 256;
    int gemm_blocks = (N_NODES + 127) / 128;

    // CSR build (4 launches)
    zero_deg<<<(N_NODES + 255) / 256, 256>>>();
    hist_kernel<<<eb, 256>>>(ei);
    scan_fused<<<1, 1024>>>();
    fill_kernel<<<eb, 256>>>(ei);

    // Layer 1 (gather fused into GEMM)
    sage_gemm_fused<1><<<gemm_blocks, 256, TCSM>>>(x, Wl1, Wr1, b1, out);
    // Layer 2
    sage_gemm_fused<2><<<gemm_blocks, 256, TCSM>>>(x, Wl2, Wr2, b2, out);
}

// round 8
// speedup vs baseline: 1.3964x; 1.3964x over previous
#include <cuda_runtime.h>
#include <cuda_bf16.h>
#include <cstdint>

#define N_NODES 50000
#define N_EDGES 600000
#define D 128

// ---------------------------------------------------------------------------
// Scratch (allocation-free rule: __device__ globals)
// ---------------------------------------------------------------------------
__device__ float g_mean[(size_t)N_NODES * D];  // gather output
__device__ float g_h[(size_t)N_NODES * D];     // layer-1 activations
__device__ int   g_deg[N_NODES];
__device__ int   g_cursor[N_NODES];
__device__ int   g_rowptr[N_NODES + 1];
__device__ int   g_esrc[N_EDGES];

__device__ __forceinline__ float to_tf32(float f) {
    float r;
    asm("cvt.rna.tf32.f32 %0, %1;" : "=f"(r) : "f"(f));
    return r;
}

// ---------------------------------------------------------------------------
// CSR build: 4 kernels
// ---------------------------------------------------------------------------
__global__ void zero_deg() {
    int i = blockIdx.x * blockDim.x + threadIdx.x;
    if (i < N_NODES) g_deg[i] = 0;
}

__global__ void hist_kernel(const int* __restrict__ eidx) {
    int e = blockIdx.x * blockDim.x + threadIdx.x;
    if (e < N_EDGES) atomicAdd(&g_deg[__ldg(&eidx[N_EDGES + e])], 1);
}

// Single-CTA scan over all 50000 degrees: thread t owns 49 contiguous nodes.
// Emits rowptr AND cursor (= exclusive prefix) for the fill pass.
__global__ void scan_fused() {
    __shared__ int wsum[32];
    const int C = (N_NODES + 1023) / 1024;   // 49
    int t = threadIdx.x, lane = t & 31, w = t >> 5;
    int beg = t * C, end = min(beg + C, N_NODES);

    int local = 0;
    for (int i = beg; i < end; i++) local += g_deg[i];

    int inc = local;
#pragma unroll
    for (int o = 1; o < 32; o <<= 1) {
        int u = __shfl_up_sync(0xffffffffu, inc, o);
        if (lane >= o) inc += u;
    }
    if (lane == 31) wsum[w] = inc;
    __syncthreads();
    if (w == 0) {
        int v = wsum[lane];
        int i2 = v;
#pragma unroll
        for (int o = 1; o < 32; o <<= 1) {
            int u = __shfl_up_sync(0xffffffffu, i2, o);
            if (lane >= o) i2 += u;
        }
        wsum[lane] = i2 - v;   // exclusive warp offsets
    }
    __syncthreads();

    int run = wsum[w] + (inc - local);   // thread's exclusive prefix
    for (int i = beg; i < end; i++) {
        int d = g_deg[i];
        g_cursor[i] = run;
        run += d;
        g_rowptr[i + 1] = run;
    }
    if (t == 0) g_rowptr[0] = 0;
}

__global__ void fill_kernel(const int* __restrict__ eidx) {
    int e = blockIdx.x * blockDim.x + threadIdx.x;
    if (e >= N_EDGES) return;
    int s = __ldg(&eidx[e]);
    int d = __ldg(&eidx[N_EDGES + e]);
    int slot = atomicAdd(&g_cursor[d], 1);
    g_esrc[slot] = s;
}

// ---------------------------------------------------------------------------
// Gather-side mean aggregation: one warp per dst node, register accumulation.
// High occupancy (no smem, 16 regs) is what hides the L2 gather latency —
// fusing this into the 1-CTA/SM GEMM regressed 2x (R7 post-mortem).
// ---------------------------------------------------------------------------
template <int LAYER>
__global__ void gather_kernel(const float* __restrict__ x_in) {
    int warp = (blockIdx.x * blockDim.x + threadIdx.x) >> 5;
    int lane = threadIdx.x & 31;
    if (warp >= N_NODES) return;

    const float* feat = (LAYER == 1) ? x_in : g_h;

    int beg = __ldg(&g_rowptr[warp]);
    int end = __ldg(&g_rowptr[warp + 1]);

    float4 acc = make_float4(0.f, 0.f, 0.f, 0.f);
    int j = beg;
    for (; j + 4 <= end; j += 4) {
        int s0 = __ldg(&g_esrc[j + 0]);
        int s1 = __ldg(&g_esrc[j + 1]);
        int s2 = __ldg(&g_esrc[j + 2]);
        int s3 = __ldg(&g_esrc[j + 3]);
        float4 v0 = __ldg(reinterpret_cast<const float4*>(feat + (size_t)s0 * D) + lane);
        float4 v1 = __ldg(reinterpret_cast<const float4*>(feat + (size_t)s1 * D) + lane);
        float4 v2 = __ldg(reinterpret_cast<const float4*>(feat + (size_t)s2 * D) + lane);
        float4 v3 = __ldg(reinterpret_cast<const float4*>(feat + (size_t)s3 * D) + lane);
        acc.x += (v0.x + v1.x) + (v2.x + v3.x);
        acc.y += (v0.y + v1.y) + (v2.y + v3.y);
        acc.z += (v0.z + v1.z) + (v2.z + v3.z);
        acc.w += (v0.w + v1.w) + (v2.w + v3.w);
    }
    for (; j < end; j++) {
        int s = __ldg(&g_esrc[j]);
        float4 v = __ldg(reinterpret_cast<const float4*>(feat + (size_t)s * D) + lane);
        acc.x += v.x; acc.y += v.y; acc.z += v.z; acc.w += v.w;
    }

    float inv = 1.0f / fmaxf((float)(end - beg), 1.0f);
    acc.x *= inv; acc.y *= inv; acc.z *= inv; acc.w *= inv;
    reinterpret_cast<float4*>(g_mean + (size_t)warp * D)[lane] = acc;
}

// ---------------------------------------------------------------------------
// tf32 mma.sync GEMM: out = mean @ Wl + feat @ Wr + b (+relu L1)
// CTA = 128 rows x 128 cols, 8 warps, each warp an m16 x n128 strip.
// K=256 via two staged passes, fp32 register accumulators.
// ---------------------------------------------------------------------------
#define ASA 132
#define WSB 136
#define TCSM ((128 * ASA + 128 * WSB) * 4)   // 134 KB

__device__ __forceinline__ void mma_tf32(float c[4], uint32_t a0, uint32_t a1,
                                         uint32_t a2, uint32_t a3,
                                         uint32_t b0, uint32_t b1) {
    asm volatile(
        "mma.sync.aligned.m16n8k8.row.col.f32.tf32.tf32.f32 "
        "{%0,%1,%2,%3}, {%4,%5,%6,%7}, {%8,%9}, {%0,%1,%2,%3};"
        : "+f"(c[0]), "+f"(c[1]), "+f"(c[2]), "+f"(c[3])
        : "r"(a0), "r"(a1), "r"(a2), "r"(a3), "r"(b0), "r"(b1));
}

template <int LAYER>
__global__ void __launch_bounds__(256, 1)
sage_gemm_mma(const float* __restrict__ x_in,
              const float* __restrict__ Wl, const float* __restrict__ Wr,
              const float* __restrict__ bias, float* __restrict__ d_out) {
    extern __shared__ float sm[];
    float* sA = sm;                 // [128][ASA]
    float* sW = sm + 128 * ASA;     // [128][WSB]

    int tid = threadIdx.x;
    int wid = tid >> 5;
    int lane = tid & 31;
    int gid = lane >> 2;            // 0..7
    int tig = lane & 3;             // 0..3
    int base = blockIdx.x * 128;

    const float* feat = (LAYER == 1) ? x_in : g_h;
    float* out        = (LAYER == 1) ? g_h : d_out;

    float c[16][4];
#pragma unroll
    for (int nt = 0; nt < 16; nt++)
#pragma unroll
        for (int q = 0; q < 4; q++) c[nt][q] = 0.f;

#pragma unroll
    for (int pass = 0; pass < 2; pass++) {
        const float* Asrc = (pass == 0) ? g_mean : feat;
        const float* Wsrc = (pass == 0) ? Wl : Wr;

        if (pass) __syncthreads();   // all warps done reading pass-0 tiles

        // Stage A: 128 rows x 32 float4, tf32-rounded
        for (int e = tid; e < 128 * 32; e += 256) {
            int r = e >> 5, c4 = e & 31;
            int g = base + r;
            float4 v = make_float4(0.f, 0.f, 0.f, 0.f);
            if (g < N_NODES)
                v = __ldg(reinterpret_cast<const float4*>(Asrc + (size_t)g * D) + c4);
            v.x = to_tf32(v.x); v.y = to_tf32(v.y);
            v.z = to_tf32(v.z); v.w = to_tf32(v.w);
            *reinterpret_cast<float4*>(sA + r * ASA + c4 * 4) = v;
        }
        // Stage W (row-major [k][n], consumed as col-frag B)
        for (int e = tid; e < 128 * 32; e += 256) {
            int r = e >> 5, c4 = e & 31;
            float4 v = __ldg(reinterpret_cast<const float4*>(Wsrc + (size_t)r * D) + c4);
            v.x = to_tf32(v.x); v.y = to_tf32(v.y);
            v.z = to_tf32(v.z); v.w = to_tf32(v.w);
            *reinterpret_cast<float4*>(sW + r * WSB + c4 * 4) = v;
        }
        __syncthreads();

        const float* Awarp = sA + (wid * 16 + gid) * ASA + tig;
#pragma unroll 4
        for (int ks = 0; ks < 16; ks++) {
            const float* ap = Awarp + ks * 8;
            uint32_t a0 = __float_as_uint(ap[0]);
            uint32_t a1 = __float_as_uint(ap[8 * ASA]);
            uint32_t a2 = __float_as_uint(ap[4]);
            uint32_t a3 = __float_as_uint(ap[8 * ASA + 4]);
            const float* bp = sW + (ks * 8 + tig) * WSB + gid;
#pragma unroll
            for (int nt = 0; nt < 16; nt++) {
                uint32_t b0 = __float_as_uint(bp[nt * 8]);
                uint32_t b1 = __float_as_uint(bp[4 * WSB + nt * 8]);
                mma_tf32(c[nt], a0, a1, a2, a3, b0, b1);
            }
        }
    }

    // Epilogue: bias (+relu), direct register->gmem store
    int row0 = base + wid * 16 + gid;
#pragma unroll
    for (int nt = 0; nt < 16; nt++) {
        int col = nt * 8 + 2 * tig;
        float2 bb = *reinterpret_cast<const float2*>(bias + col);
        float o0 = c[nt][0] + bb.x, o1 = c[nt][1] + bb.y;
        float o2 = c[nt][2] + bb.x, o3 = c[nt][3] + bb.y;
        if (LAYER == 1) {
            o0 = fmaxf(o0, 0.f); o1 = fmaxf(o1, 0.f);
            o2 = fmaxf(o2, 0.f); o3 = fmaxf(o3, 0.f);
        }
        if (row0 < N_NODES)
            *reinterpret_cast<float2*>(out + (size_t)row0 * D + col) = make_float2(o0, o1);
        if (row0 + 8 < N_NODES)
            *reinterpret_cast<float2*>(out + (size_t)(row0 + 8) * D + col) = make_float2(o2, o3);
    }
}

// ---------------------------------------------------------------------------
extern "C" void kernel_launch(void* const* d_in, const int* in_sizes, int n_in,
                              void* d_out, int out_size) {
    const float* x       = (const float*)d_in[0];
    const int* ei        = (const int*)d_in[1];   // int32 (JAX x64 disabled)
    const float* Wl1     = (const float*)d_in[2];
    const float* Wr1     = (const float*)d_in[3];
    const float* b1      = (const float*)d_in[4];
    const float* Wl2     = (const float*)d_in[5];
    const float* Wr2     = (const float*)d_in[6];
    const float* b2      = (const float*)d_in[7];
    float* out           = (float*)d_out;

    cudaFuncSetAttribute(sage_gemm_mma<1>,
                         cudaFuncAttributeMaxDynamicSharedMemorySize, TCSM);
    cudaFuncSetAttribute(sage_gemm_mma<2>,
                         cudaFuncAttributeMaxDynamicSharedMemorySize, TCSM);

    int eb = (N_EDGES + 255) / 256;
    int gather_blocks = (N_NODES * 32 + 255) / 256;
    int gemm_blocks = (N_NODES + 127) / 128;

    // CSR build (4 launches)
    zero_deg<<<(N_NODES + 255) / 256, 256>>>();
    hist_kernel<<<eb, 256>>>(ei);
    scan_fused<<<1, 1024>>>();
    fill_kernel<<<eb, 256>>>(ei);

    // Layer 1
    gather_kernel<1><<<gather_blocks, 256>>>(x);
    sage_gemm_mma<1><<<gemm_blocks, 256, TCSM>>>(x, Wl1, Wr1, b1, out);

    // Layer 2
    gather_kernel<2><<<gather_blocks, 256>>>(x);
    sage_gemm_mma<2><<<gemm_blocks, 256, TCSM>>>(x, Wl2, Wr2, b2, out);
}

// round 9
// speedup vs baseline: 1.8598x; 1.3319x over previous
#include <cuda_runtime.h>
#include <cuda_bf16.h>
#include <cstdint>

#define N_NODES 50000
#define N_EDGES 600000
#define D 128
#define SCAN_B 1024
#define NB ((N_NODES + SCAN_B - 1) / SCAN_B)   // 49

// ---------------------------------------------------------------------------
// Scratch (allocation-free rule: __device__ globals)
// ---------------------------------------------------------------------------
__device__ float g_mean[(size_t)N_NODES * D];  // gather output
__device__ float g_h[(size_t)N_NODES * D];     // layer-1 activations
__device__ int   g_deg[N_NODES];
__device__ int   g_cursor[N_NODES];
__device__ int   g_rowptr[N_NODES + 1];
__device__ int   g_bsum[NB];
__device__ int   g_esrc[N_EDGES];

__device__ __forceinline__ float to_tf32(float f) {
    float r;
    asm("cvt.rna.tf32.f32 %0, %1;" : "=f"(r) : "f"(f));
    return r;
}

// ---------------------------------------------------------------------------
// CSR build: 5 kernels, all coalesced full-chip (R8 single-CTA scan was the
// regression: per-thread-contiguous layout = 32 lines per warp access).
// ---------------------------------------------------------------------------
__global__ void zero_deg() {
    int i = blockIdx.x * blockDim.x + threadIdx.x;
    if (i < N_NODES) g_deg[i] = 0;
}

__global__ void hist_kernel(const int* __restrict__ eidx) {
    int e = blockIdx.x * blockDim.x + threadIdx.x;
    if (e < N_EDGES) atomicAdd(&g_deg[__ldg(&eidx[N_EDGES + e])], 1);
}

// Block-local inclusive scan (warp shfl), coalesced. rowptr gets block-local
// inclusive values; bsum gets block totals.
__global__ void scan_block() {
    __shared__ int wsum[32];
    int tid = threadIdx.x, lane = tid & 31, w = tid >> 5;
    int gid = blockIdx.x * SCAN_B + tid;
    int v = (gid < N_NODES) ? g_deg[gid] : 0;
    int inc = v;
#pragma unroll
    for (int o = 1; o < 32; o <<= 1) {
        int u = __shfl_up_sync(0xffffffffu, inc, o);
        if (lane >= o) inc += u;
    }
    if (lane == 31) wsum[w] = inc;
    __syncthreads();
    if (w == 0) {
        int t = wsum[lane];
        int i2 = t;
#pragma unroll
        for (int o = 1; o < 32; o <<= 1) {
            int u = __shfl_up_sync(0xffffffffu, i2, o);
            if (lane >= o) i2 += u;
        }
        wsum[lane] = i2 - t;   // exclusive warp offsets
    }
    __syncthreads();
    int incl = wsum[w] + inc;
    if (gid < N_NODES) g_rowptr[gid + 1] = incl;
    if (tid == SCAN_B - 1) g_bsum[blockIdx.x] = incl;
}

// Adds block offsets; each block re-scans the 49 partials itself (cheap, one
// warp) — no separate scan_partials launch. Also emits cursor = rowptr copy.
__global__ void scan_add() {
    __shared__ int s_ex[64];
    int tid = threadIdx.x, lane = tid & 31;
    if (tid < 32) {
        int v0 = (lane < NB) ? g_bsum[lane] : 0;
        int v1 = (32 + lane < NB) ? g_bsum[32 + lane] : 0;
        int i0 = v0, i1 = v1;
#pragma unroll
        for (int o = 1; o < 32; o <<= 1) {
            int u0 = __shfl_up_sync(0xffffffffu, i0, o);
            int u1 = __shfl_up_sync(0xffffffffu, i1, o);
            if (lane >= o) { i0 += u0; i1 += u1; }
        }
        int tot0 = __shfl_sync(0xffffffffu, i0, 31);
        s_ex[lane] = i0 - v0;
        s_ex[32 + lane] = i1 - v1 + tot0;
    }
    __syncthreads();
    int off = s_ex[blockIdx.x];
    int gid = blockIdx.x * SCAN_B + tid;
    if (gid < N_NODES) {
        int rp = g_rowptr[gid + 1] + off;
        g_rowptr[gid + 1] = rp;
        if (gid + 1 < N_NODES) g_cursor[gid + 1] = rp;
    }
    if (gid == 0) { g_rowptr[0] = 0; g_cursor[0] = 0; }
}

__global__ void fill_kernel(const int* __restrict__ eidx) {
    int e = blockIdx.x * blockDim.x + threadIdx.x;
    if (e >= N_EDGES) return;
    int s = __ldg(&eidx[e]);
    int d = __ldg(&eidx[N_EDGES + e]);
    int slot = atomicAdd(&g_cursor[d], 1);
    g_esrc[slot] = s;
}

// ---------------------------------------------------------------------------
// Gather-side mean aggregation: one warp per dst node, register accumulation.
// High occupancy (no smem, low regs) hides the L2 gather latency — this is
// at the L2-bandwidth roofline (~27us/layer); do not fuse (R7 post-mortem).
// ---------------------------------------------------------------------------
template <int LAYER>
__global__ void gather_kernel(const float* __restrict__ x_in) {
    int warp = (blockIdx.x * blockDim.x + threadIdx.x) >> 5;
    int lane = threadIdx.x & 31;
    if (warp >= N_NODES) return;

    const float* feat = (LAYER == 1) ? x_in : g_h;

    int beg = __ldg(&g_rowptr[warp]);
    int end = __ldg(&g_rowptr[warp + 1]);

    float4 acc = make_float4(0.f, 0.f, 0.f, 0.f);
    int j = beg;
    for (; j + 4 <= end; j += 4) {
        int s0 = __ldg(&g_esrc[j + 0]);
        int s1 = __ldg(&g_esrc[j + 1]);
        int s2 = __ldg(&g_esrc[j + 2]);
        int s3 = __ldg(&g_esrc[j + 3]);
        float4 v0 = __ldg(reinterpret_cast<const float4*>(feat + (size_t)s0 * D) + lane);
        float4 v1 = __ldg(reinterpret_cast<const float4*>(feat + (size_t)s1 * D) + lane);
        float4 v2 = __ldg(reinterpret_cast<const float4*>(feat + (size_t)s2 * D) + lane);
        float4 v3 = __ldg(reinterpret_cast<const float4*>(feat + (size_t)s3 * D) + lane);
        acc.x += (v0.x + v1.x) + (v2.x + v3.x);
        acc.y += (v0.y + v1.y) + (v2.y + v3.y);
        acc.z += (v0.z + v1.z) + (v2.z + v3.z);
        acc.w += (v0.w + v1.w) + (v2.w + v3.w);
    }
    for (; j < end; j++) {
        int s = __ldg(&g_esrc[j]);
        float4 v = __ldg(reinterpret_cast<const float4*>(feat + (size_t)s * D) + lane);
        acc.x += v.x; acc.y += v.y; acc.z += v.z; acc.w += v.w;
    }

    float inv = 1.0f / fmaxf((float)(end - beg), 1.0f);
    acc.x *= inv; acc.y *= inv; acc.z *= inv; acc.w *= inv;
    reinterpret_cast<float4*>(g_mean + (size_t)warp * D)[lane] = acc;
}

// ---------------------------------------------------------------------------
// tf32 mma.sync GEMM: out = mean @ Wl + feat @ Wr + b (+relu L1)
// CTA = 128 rows x 128 cols, 8 warps. Both weight tiles staged ONCE
// (sW0 + sW1 + sA = 202 KB); only A restaged between passes.
// ---------------------------------------------------------------------------
#define ASA 132
#define WSB 136
#define TCSM ((2 * 128 * WSB + 128 * ASA) * 4)   // 202 KB

__device__ __forceinline__ void mma_tf32(float c[4], uint32_t a0, uint32_t a1,
                                         uint32_t a2, uint32_t a3,
                                         uint32_t b0, uint32_t b1) {
    asm volatile(
        "mma.sync.aligned.m16n8k8.row.col.f32.tf32.tf32.f32 "
        "{%0,%1,%2,%3}, {%4,%5,%6,%7}, {%8,%9}, {%0,%1,%2,%3};"
        : "+f"(c[0]), "+f"(c[1]), "+f"(c[2]), "+f"(c[3])
        : "r"(a0), "r"(a1), "r"(a2), "r"(a3), "r"(b0), "r"(b1));
}

template <int LAYER>
__global__ void __launch_bounds__(256, 1)
sage_gemm_mma(const float* __restrict__ x_in,
              const float* __restrict__ Wl, const float* __restrict__ Wr,
              const float* __restrict__ bias, float* __restrict__ d_out) {
    extern __shared__ float sm[];
    float* sW0 = sm;                    // [128][WSB]
    float* sW1 = sm + 128 * WSB;        // [128][WSB]
    float* sA  = sm + 2 * 128 * WSB;    // [128][ASA]

    int tid = threadIdx.x;
    int wid = tid >> 5;
    int lane = tid & 31;
    int gid = lane >> 2;            // 0..7
    int tig = lane & 3;             // 0..3
    int base = blockIdx.x * 128;

    const float* feat = (LAYER == 1) ? x_in : g_h;
    float* out        = (LAYER == 1) ? g_h : d_out;

    // Stage both W tiles + A(mean) up front
    for (int e = tid; e < 128 * 32; e += 256) {
        int r = e >> 5, c4 = e & 31;
        float4 v0 = __ldg(reinterpret_cast<const float4*>(Wl + (size_t)r * D) + c4);
        float4 v1 = __ldg(reinterpret_cast<const float4*>(Wr + (size_t)r * D) + c4);
        v0.x = to_tf32(v0.x); v0.y = to_tf32(v0.y); v0.z = to_tf32(v0.z); v0.w = to_tf32(v0.w);
        v1.x = to_tf32(v1.x); v1.y = to_tf32(v1.y); v1.z = to_tf32(v1.z); v1.w = to_tf32(v1.w);
        *reinterpret_cast<float4*>(sW0 + r * WSB + c4 * 4) = v0;
        *reinterpret_cast<float4*>(sW1 + r * WSB + c4 * 4) = v1;

        int g = base + r;
        float4 va = make_float4(0.f, 0.f, 0.f, 0.f);
        if (g < N_NODES)
            va = __ldg(reinterpret_cast<const float4*>(g_mean + (size_t)g * D) + c4);
        va.x = to_tf32(va.x); va.y = to_tf32(va.y); va.z = to_tf32(va.z); va.w = to_tf32(va.w);
        *reinterpret_cast<float4*>(sA + r * ASA + c4 * 4) = va;
    }
    __syncthreads();

    float c[16][4];
#pragma unroll
    for (int nt = 0; nt < 16; nt++)
#pragma unroll
        for (int q = 0; q < 4; q++) c[nt][q] = 0.f;

#pragma unroll
    for (int pass = 0; pass < 2; pass++) {
        if (pass) {
            __syncthreads();   // pass-0 A fully consumed
            for (int e = tid; e < 128 * 32; e += 256) {
                int r = e >> 5, c4 = e & 31;
                int g = base + r;
                float4 v = make_float4(0.f, 0.f, 0.f, 0.f);
                if (g < N_NODES)
                    v = __ldg(reinterpret_cast<const float4*>(feat + (size_t)g * D) + c4);
                v.x = to_tf32(v.x); v.y = to_tf32(v.y);
                v.z = to_tf32(v.z); v.w = to_tf32(v.w);
                *reinterpret_cast<float4*>(sA + r * ASA + c4 * 4) = v;
            }
            __syncthreads();
        }

        const float* sW = (pass == 0) ? sW0 : sW1;
        const float* Awarp = sA + (wid * 16 + gid) * ASA + tig;
#pragma unroll 4
        for (int ks = 0; ks < 16; ks++) {
            const float* ap = Awarp + ks * 8;
            uint32_t a0 = __float_as_uint(ap[0]);
            uint32_t a1 = __float_as_uint(ap[8 * ASA]);
            uint32_t a2 = __float_as_uint(ap[4]);
            uint32_t a3 = __float_as_uint(ap[8 * ASA + 4]);
            const float* bp = sW + (ks * 8 + tig) * WSB + gid;
#pragma unroll
            for (int nt = 0; nt < 16; nt++) {
                uint32_t b0 = __float_as_uint(bp[nt * 8]);
                uint32_t b1 = __float_as_uint(bp[4 * WSB + nt * 8]);
                mma_tf32(c[nt], a0, a1, a2, a3, b0, b1);
            }
        }
    }

    // Epilogue: bias (+relu), direct register->gmem store
    int row0 = base + wid * 16 + gid;
#pragma unroll
    for (int nt = 0; nt < 16; nt++) {
        int col = nt * 8 + 2 * tig;
        float2 bb = *reinterpret_cast<const float2*>(bias + col);
        float o0 = c[nt][0] + bb.x, o1 = c[nt][1] + bb.y;
        float o2 = c[nt][2] + bb.x, o3 = c[nt][3] + bb.y;
        if (LAYER == 1) {
            o0 = fmaxf(o0, 0.f); o1 = fmaxf(o1, 0.f);
            o2 = fmaxf(o2, 0.f); o3 = fmaxf(o3, 0.f);
        }
        if (row0 < N_NODES)
            *reinterpret_cast<float2*>(out + (size_t)row0 * D + col) = make_float2(o0, o1);
        if (row0 + 8 < N_NODES)
            *reinterpret_cast<float2*>(out + (size_t)(row0 + 8) * D + col) = make_float2(o2, o3);
    }
}

// ---------------------------------------------------------------------------
extern "C" void kernel_launch(void* const* d_in, const int* in_sizes, int n_in,
                              void* d_out, int out_size) {
    const float* x       = (const float*)d_in[0];
    const int* ei        = (const int*)d_in[1];   // int32 (JAX x64 disabled)
    const float* Wl1     = (const float*)d_in[2];
    const float* Wr1     = (const float*)d_in[3];
    const float* b1      = (const float*)d_in[4];
    const float* Wl2     = (const float*)d_in[5];
    const float* Wr2     = (const float*)d_in[6];
    const float* b2      = (const float*)d_in[7];
    float* out           = (float*)d_out;

    cudaFuncSetAttribute(sage_gemm_mma<1>,
                         cudaFuncAttributeMaxDynamicSharedMemorySize, TCSM);
    cudaFuncSetAttribute(sage_gemm_mma<2>,
                         cudaFuncAttributeMaxDynamicSharedMemorySize, TCSM);

    int eb = (N_EDGES + 255) / 256;
    int gather_blocks = (N_NODES * 32 + 255) / 256;
    int gemm_blocks = (N_NODES + 127) / 128;

    // CSR build (5 launches, all coalesced)
    zero_deg<<<(N_NODES + 255) / 256, 256>>>();
    hist_kernel<<<eb, 256>>>(ei);
    scan_block<<<NB, SCAN_B>>>();
    scan_add<<<NB, SCAN_B>>>();
    fill_kernel<<<eb, 256>>>(ei);

    // Layer 1
    gather_kernel<1><<<gather_blocks, 256>>>(x);
    sage_gemm_mma<1><<<gemm_blocks, 256, TCSM>>>(x, Wl1, Wr1, b1, out);

    // Layer 2
    gather_kernel<2><<<gather_blocks, 256>>>(x);
    sage_gemm_mma<2><<<gemm_blocks, 256, TCSM>>>(x, Wl2, Wr2, b2, out);
}

// round 10
// speedup vs baseline: 2.0340x; 1.0937x over previous
#include <cuda_runtime.h>
#include <cuda_bf16.h>
#include <cstdint>

#define N_NODES 50000
#define N_EDGES 600000
#define D 128
#define SCAN_B 1024
#define NB ((N_NODES + SCAN_B - 1) / SCAN_B)   // 49

// ---------------------------------------------------------------------------
// Scratch (allocation-free rule: __device__ globals)
// ---------------------------------------------------------------------------
__device__ float g_mean[(size_t)N_NODES * D];  // gather output
__device__ float g_h[(size_t)N_NODES * D];     // layer-1 activations
__device__ int   g_deg[N_NODES];
__device__ int   g_cursor[N_NODES];
__device__ int   g_rowptr[N_NODES + 1];
__device__ int   g_bsum[NB];
__device__ int   g_esrc[N_EDGES];

__device__ __forceinline__ float to_tf32(float f) {
    float r;
    asm("cvt.rna.tf32.f32 %0, %1;" : "=f"(r) : "f"(f));
    return r;
}

// ---------------------------------------------------------------------------
// CSR build: 5 kernels, all coalesced full-chip
// ---------------------------------------------------------------------------
__global__ void zero_deg() {
    int i = blockIdx.x * blockDim.x + threadIdx.x;
    if (i < N_NODES) g_deg[i] = 0;
}

__global__ void hist_kernel(const int* __restrict__ eidx) {
    int e = blockIdx.x * blockDim.x + threadIdx.x;
    if (e < N_EDGES) atomicAdd(&g_deg[__ldg(&eidx[N_EDGES + e])], 1);
}

// Block-local inclusive scan (warp shfl), coalesced.
__global__ void scan_block() {
    __shared__ int wsum[32];
    int tid = threadIdx.x, lane = tid & 31, w = tid >> 5;
    int gid = blockIdx.x * SCAN_B + tid;
    int v = (gid < N_NODES) ? g_deg[gid] : 0;
    int inc = v;
#pragma unroll
    for (int o = 1; o < 32; o <<= 1) {
        int u = __shfl_up_sync(0xffffffffu, inc, o);
        if (lane >= o) inc += u;
    }
    if (lane == 31) wsum[w] = inc;
    __syncthreads();
    if (w == 0) {
        int t = wsum[lane];
        int i2 = t;
#pragma unroll
        for (int o = 1; o < 32; o <<= 1) {
            int u = __shfl_up_sync(0xffffffffu, i2, o);
            if (lane >= o) i2 += u;
        }
        wsum[lane] = i2 - t;   // exclusive warp offsets
    }
    __syncthreads();
    int incl = wsum[w] + inc;
    if (gid < N_NODES) g_rowptr[gid + 1] = incl;
    if (tid == SCAN_B - 1) g_bsum[blockIdx.x] = incl;
}

// Adds block offsets; each block re-scans the 49 partials itself (one warp).
// Also emits cursor = exclusive rowptr for the fill pass.
__global__ void scan_add() {
    __shared__ int s_ex[64];
    int tid = threadIdx.x, lane = tid & 31;
    if (tid < 32) {
        int v0 = (lane < NB) ? g_bsum[lane] : 0;
        int v1 = (32 + lane < NB) ? g_bsum[32 + lane] : 0;
        int i0 = v0, i1 = v1;
#pragma unroll
        for (int o = 1; o < 32; o <<= 1) {
            int u0 = __shfl_up_sync(0xffffffffu, i0, o);
            int u1 = __shfl_up_sync(0xffffffffu, i1, o);
            if (lane >= o) { i0 += u0; i1 += u1; }
        }
        int tot0 = __shfl_sync(0xffffffffu, i0, 31);
        s_ex[lane] = i0 - v0;
        s_ex[32 + lane] = i1 - v1 + tot0;
    }
    __syncthreads();
    int off = s_ex[blockIdx.x];
    int gid = blockIdx.x * SCAN_B + tid;
    if (gid < N_NODES) {
        int rp = g_rowptr[gid + 1] + off;
        g_rowptr[gid + 1] = rp;
        if (gid + 1 < N_NODES) g_cursor[gid + 1] = rp;
    }
    if (gid == 0) { g_rowptr[0] = 0; g_cursor[0] = 0; }
}

__global__ void fill_kernel(const int* __restrict__ eidx) {
    int e = blockIdx.x * blockDim.x + threadIdx.x;
    if (e >= N_EDGES) return;
    int s = __ldg(&eidx[e]);
    int d = __ldg(&eidx[N_EDGES + e]);
    int slot = atomicAdd(&g_cursor[d], 1);
    g_esrc[slot] = s;
}

// ---------------------------------------------------------------------------
// Gather-side mean aggregation: one warp per dst node, register accumulation.
// High occupancy hides L2 gather latency; at the LTS-bandwidth roofline.
// ---------------------------------------------------------------------------
template <int LAYER>
__global__ void gather_kernel(const float* __restrict__ x_in) {
    int warp = (blockIdx.x * blockDim.x + threadIdx.x) >> 5;
    int lane = threadIdx.x & 31;
    if (warp >= N_NODES) return;

    const float* feat = (LAYER == 1) ? x_in : g_h;

    int beg = __ldg(&g_rowptr[warp]);
    int end = __ldg(&g_rowptr[warp + 1]);

    float4 acc = make_float4(0.f, 0.f, 0.f, 0.f);
    int j = beg;
    for (; j + 4 <= end; j += 4) {
        int s0 = __ldg(&g_esrc[j + 0]);
        int s1 = __ldg(&g_esrc[j + 1]);
        int s2 = __ldg(&g_esrc[j + 2]);
        int s3 = __ldg(&g_esrc[j + 3]);
        float4 v0 = __ldg(reinterpret_cast<const float4*>(feat + (size_t)s0 * D) + lane);
        float4 v1 = __ldg(reinterpret_cast<const float4*>(feat + (size_t)s1 * D) + lane);
        float4 v2 = __ldg(reinterpret_cast<const float4*>(feat + (size_t)s2 * D) + lane);
        float4 v3 = __ldg(reinterpret_cast<const float4*>(feat + (size_t)s3 * D) + lane);
        acc.x += (v0.x + v1.x) + (v2.x + v3.x);
        acc.y += (v0.y + v1.y) + (v2.y + v3.y);
        acc.z += (v0.z + v1.z) + (v2.z + v3.z);
        acc.w += (v0.w + v1.w) + (v2.w + v3.w);
    }
    for (; j < end; j++) {
        int s = __ldg(&g_esrc[j]);
        float4 v = __ldg(reinterpret_cast<const float4*>(feat + (size_t)s * D) + lane);
        acc.x += v.x; acc.y += v.y; acc.z += v.z; acc.w += v.w;
    }

    float inv = 1.0f / fmaxf((float)(end - beg), 1.0f);
    acc.x *= inv; acc.y *= inv; acc.z *= inv; acc.w *= inv;
    reinterpret_cast<float4*>(g_mean + (size_t)warp * D)[lane] = acc;
}

// ---------------------------------------------------------------------------
// tf32 mma.sync GEMM (exact R6 structure — the fastest measured variant):
// CTA = 128 rows x 128 cols, 8 warps. K=256 via two staged passes
// (A+W per pass, 134 KB smem), fp32 register accumulators.
// ---------------------------------------------------------------------------
#define ASA 132
#define WSB 136
#define TCSM ((128 * ASA + 128 * WSB) * 4)   // 134 KB

__device__ __forceinline__ void mma_tf32(float c[4], uint32_t a0, uint32_t a1,
                                         uint32_t a2, uint32_t a3,
                                         uint32_t b0, uint32_t b1) {
    asm volatile(
        "mma.sync.aligned.m16n8k8.row.col.f32.tf32.tf32.f32 "
        "{%0,%1,%2,%3}, {%4,%5,%6,%7}, {%8,%9}, {%0,%1,%2,%3};"
        : "+f"(c[0]), "+f"(c[1]), "+f"(c[2]), "+f"(c[3])
        : "r"(a0), "r"(a1), "r"(a2), "r"(a3), "r"(b0), "r"(b1));
}

template <int LAYER>
__global__ void __launch_bounds__(256, 1)
sage_gemm_mma(const float* __restrict__ x_in,
              const float* __restrict__ Wl, const float* __restrict__ Wr,
              const float* __restrict__ bias, float* __restrict__ d_out) {
    extern __shared__ float sm[];
    float* sA = sm;                 // [128][ASA]
    float* sW = sm + 128 * ASA;     // [128][WSB]

    int tid = threadIdx.x;
    int wid = tid >> 5;
    int lane = tid & 31;
    int gid = lane >> 2;            // 0..7
    int tig = lane & 3;             // 0..3
    int base = blockIdx.x * 128;

    const float* feat = (LAYER == 1) ? x_in : g_h;
    float* out        = (LAYER == 1) ? g_h : d_out;

    float c[16][4];
#pragma unroll
    for (int nt = 0; nt < 16; nt++)
#pragma unroll
        for (int q = 0; q < 4; q++) c[nt][q] = 0.f;

#pragma unroll
    for (int pass = 0; pass < 2; pass++) {
        const float* Asrc = (pass == 0) ? g_mean : feat;
        const float* Wsrc = (pass == 0) ? Wl : Wr;

        if (pass) __syncthreads();   // all warps done reading pass-0 tiles

        // Stage A: 128 rows x 32 float4, tf32-rounded
        for (int e = tid; e < 128 * 32; e += 256) {
            int r = e >> 5, c4 = e & 31;
            int g = base + r;
            float4 v = make_float4(0.f, 0.f, 0.f, 0.f);
            if (g < N_NODES)
                v = __ldg(reinterpret_cast<const float4*>(Asrc + (size_t)g * D) + c4);
            v.x = to_tf32(v.x); v.y = to_tf32(v.y);
            v.z = to_tf32(v.z); v.w = to_tf32(v.w);
            *reinterpret_cast<float4*>(sA + r * ASA + c4 * 4) = v;
        }
        // Stage W (row-major [k][n], consumed as col-frag B)
        for (int e = tid; e < 128 * 32; e += 256) {
            int r = e >> 5, c4 = e & 31;
            float4 v = __ldg(reinterpret_cast<const float4*>(Wsrc + (size_t)r * D) + c4);
            v.x = to_tf32(v.x); v.y = to_tf32(v.y);
            v.z = to_tf32(v.z); v.w = to_tf32(v.w);
            *reinterpret_cast<float4*>(sW + r * WSB + c4 * 4) = v;
        }
        __syncthreads();

        const float* Awarp = sA + (wid * 16 + gid) * ASA + tig;
#pragma unroll 4
        for (int ks = 0; ks < 16; ks++) {
            const float* ap = Awarp + ks * 8;
            uint32_t a0 = __float_as_uint(ap[0]);
            uint32_t a1 = __float_as_uint(ap[8 * ASA]);
            uint32_t a2 = __float_as_uint(ap[4]);
            uint32_t a3 = __float_as_uint(ap[8 * ASA + 4]);
            const float* bp = sW + (ks * 8 + tig) * WSB + gid;
#pragma unroll
            for (int nt = 0; nt < 16; nt++) {
                uint32_t b0 = __float_as_uint(bp[nt * 8]);
                uint32_t b1 = __float_as_uint(bp[4 * WSB + nt * 8]);
                mma_tf32(c[nt], a0, a1, a2, a3, b0, b1);
            }
        }
    }

    // Epilogue: bias (+relu), direct register->gmem store
    int row0 = base + wid * 16 + gid;
#pragma unroll
    for (int nt = 0; nt < 16; nt++) {
        int col = nt * 8 + 2 * tig;
        float2 bb = *reinterpret_cast<const float2*>(bias + col);
        float o0 = c[nt][0] + bb.x, o1 = c[nt][1] + bb.y;
        float o2 = c[nt][2] + bb.x, o3 = c[nt][3] + bb.y;
        if (LAYER == 1) {
            o0 = fmaxf(o0, 0.f); o1 = fmaxf(o1, 0.f);
            o2 = fmaxf(o2, 0.f); o3 = fmaxf(o3, 0.f);
        }
        if (row0 < N_NODES)
            *reinterpret_cast<float2*>(out + (size_t)row0 * D + col) = make_float2(o0, o1);
        if (row0 + 8 < N_NODES)
            *reinterpret_cast<float2*>(out + (size_t)(row0 + 8) * D + col) = make_float2(o2, o3);
    }
}

// ---------------------------------------------------------------------------
extern "C" void kernel_launch(void* const* d_in, const int* in_sizes, int n_in,
                              void* d_out, int out_size) {
    const float* x       = (const float*)d_in[0];
    const int* ei        = (const int*)d_in[1];   // int32 (JAX x64 disabled)
    const float* Wl1     = (const float*)d_in[2];
    const float* Wr1     = (const float*)d_in[3];
    const float* b1      = (const float*)d_in[4];
    const float* Wl2     = (const float*)d_in[5];
    const float* Wr2     = (const float*)d_in[6];
    const float* b2      = (const float*)d_in[7];
    float* out           = (float*)d_out;

    cudaFuncSetAttribute(sage_gemm_mma<1>,
                         cudaFuncAttributeMaxDynamicSharedMemorySize, TCSM);
    cudaFuncSetAttribute(sage_gemm_mma<2>,
                         cudaFuncAttributeMaxDynamicSharedMemorySize, TCSM);

    int eb = (N_EDGES + 255) / 256;
    int gather_blocks = (N_NODES * 32 + 255) / 256;
    int gemm_blocks = (N_NODES + 127) / 128;

    // CSR build (5 launches, all coalesced)
    zero_deg<<<(N_NODES + 255) / 256, 256>>>();
    hist_kernel<<<eb, 256>>>(ei);
    scan_block<<<NB, SCAN_B>>>();
    scan_add<<<NB, SCAN_B>>>();
    fill_kernel<<<eb, 256>>>(ei);

    // Layer 1
    gather_kernel<1><<<gather_blocks, 256>>>(x);
    sage_gemm_mma<1><<<gemm_blocks, 256, TCSM>>>(x, Wl1, Wr1, b1, out);

    // Layer 2
    gather_kernel<2><<<gather_blocks, 256>>>(x);
    sage_gemm_mma<2><<<gemm_blocks, 256, TCSM>>>(x, Wl2, Wr2, b2, out);
}